// round 1
// baseline (speedup 1.0000x reference)
#include <cuda_runtime.h>
#include <math.h>

// Inputs (metadata order): y[16M] f32, mu[16M] f32, std[16M] f32, idx[200*100] i32
// Output: 1 x f32 (KL scalar)

#define NUM_SAMPLES 200
#define KDOF 100

// Scratch for per-sample chi-square statistic (no device allocation allowed).
__device__ float g_q[NUM_SAMPLES];

// Kernel 1: one block per sample; thread t (t < 100) gathers one element.
__global__ void __launch_bounds__(128) chi2_kernel(
    const float* __restrict__ y,
    const float* __restrict__ mu,
    const float* __restrict__ sd,
    const int* __restrict__ idx)
{
    const int s = blockIdx.x;
    const int t = threadIdx.x;

    float v = 0.0f;
    if (t < KDOF) {
        const int i = idx[s * KDOF + t];
        // Three independent global loads -> MLP=3 per thread, latency pipelined
        const float d = (y[i] - mu[i]) / sd[i];
        v = d * d;
    }

    // Warp reduce
    #pragma unroll
    for (int o = 16; o > 0; o >>= 1)
        v += __shfl_down_sync(0xFFFFFFFFu, v, o);

    __shared__ float sm[4];
    if ((t & 31) == 0) sm[t >> 5] = v;
    __syncthreads();
    if (t == 0)
        g_q[s] = sm[0] + sm[1] + sm[2] + sm[3];
}

// Kernel 2: single block reduces q[200] -> mean, var(ddof=1), KL.
__global__ void __launch_bounds__(256) kl_kernel(float* __restrict__ out)
{
    const int t = threadIdx.x;
    const float q = (t < NUM_SAMPLES) ? g_q[t] : 0.0f;

    __shared__ float red[8];
    __shared__ float s_mean;

    // Pass 1: sum(q)
    float v = q;
    #pragma unroll
    for (int o = 16; o > 0; o >>= 1)
        v += __shfl_down_sync(0xFFFFFFFFu, v, o);
    if ((t & 31) == 0) red[t >> 5] = v;
    __syncthreads();
    if (t == 0) {
        float s = 0.0f;
        #pragma unroll
        for (int i = 0; i < 8; i++) s += red[i];
        s_mean = s / (float)NUM_SAMPLES;
    }
    __syncthreads();

    // Pass 2: sum((q - mean)^2)
    const float mean = s_mean;
    float d = (t < NUM_SAMPLES) ? (q - mean) : 0.0f;
    v = d * d;
    #pragma unroll
    for (int o = 16; o > 0; o >>= 1)
        v += __shfl_down_sync(0xFFFFFFFFu, v, o);
    if ((t & 31) == 0) red[t >> 5] = v;
    __syncthreads();

    if (t == 0) {
        float s = 0.0f;
        #pragma unroll
        for (int i = 0; i < 8; i++) s += red[i];
        const float var   = s / (float)(NUM_SAMPLES - 1);
        const float k     = (float)KDOF;
        const float two_k = 2.0f * k;
        const float dm    = mean - k;
        const float kl = 0.5f * logf(two_k / var)
                       + (var + dm * dm) / (2.0f * two_k)
                       - 0.5f;
        out[0] = kl;
    }
}

extern "C" void kernel_launch(void* const* d_in, const int* in_sizes, int n_in,
                              void* d_out, int out_size)
{
    const float* y   = (const float*)d_in[0];
    const float* mu  = (const float*)d_in[1];
    const float* sd  = (const float*)d_in[2];
    const int*   idx = (const int*)d_in[3];
    float* out = (float*)d_out;

    chi2_kernel<<<NUM_SAMPLES, 128>>>(y, mu, sd, idx);
    kl_kernel<<<1, 256>>>(out);
}